// round 1
// baseline (speedup 1.0000x reference)
#include <cuda_runtime.h>
#include <cstdint>

// Problem constants (B=1)
static constexpr int C_   = 256;
static constexpr int HW_  = 4096;     // 64*64
static constexpr int S_   = 32768;    // 8*64*64
static constexpr int SA_  = 20480;    // 5*64*64 active (last 5 frames)
static constexpr int S0_  = S_ - SA_; // 12288
static constexpr float INV_TEMP = 10.0f;

// Scratch (device globals; no allocation allowed)
__device__ __align__(16) float g_WqT[C_ * C_];
__device__ __align__(16) float g_WkT[C_ * C_];
__device__ __align__(16) float g_Q  [C_ * HW_];   // q logits -> q softmax (rows=o, cols=hw)
__device__ __align__(16) float g_Kt [SA_ * C_];   // k logits transposed -> softmax rows (rows=j, cols=o)
__device__ __align__(16) float g_T  [C_ * C_];    // T[a,c'] = sum_j Vin[a,j]*Ks[j,c']
__device__ __align__(16) float g_M  [C_ * C_];    // M = Wv @ T

// ---------------------------------------------------------------------------
// 256x256 transpose (for Wq, Wk so GEMM loads are coalesced)
// ---------------------------------------------------------------------------
__global__ void transpose256_kernel(const float* __restrict__ in, float* __restrict__ out)
{
    __shared__ float tile[32][33];
    int x = blockIdx.x * 32 + threadIdx.x;
    int y = blockIdx.y * 32 + threadIdx.y;
#pragma unroll
    for (int i = 0; i < 32; i += 8)
        tile[threadIdx.y + i][threadIdx.x] = in[(y + i) * C_ + x];
    __syncthreads();
    x = blockIdx.y * 32 + threadIdx.x;
    y = blockIdx.x * 32 + threadIdx.y;
#pragma unroll
    for (int i = 0; i < 32; i += 8)
        out[(y + i) * C_ + x] = tile[threadIdx.x][threadIdx.y + i];
}

// ---------------------------------------------------------------------------
// GEMM TN: Out[m,n] = sum_k A[k*lda + m] * B[k*ldb + n]
// (A is K-major over m-contiguous rows; B likewise; both loads coalesced.)
// BM=BN=128, BK=8, 256 threads, 8x8 microtile. All dims divide evenly.
// ---------------------------------------------------------------------------
template<int BM, int BN, int BK, int TM, int TN>
__global__ void __launch_bounds__(256, 2) gemm_tn_kernel(
    const float* __restrict__ A, int lda,
    const float* __restrict__ B, int ldb,
    float* __restrict__ Cm, int ldc, int Kdim)
{
    __shared__ float As[BK][BM];
    __shared__ float Bs[BK][BN];
    const int m0 = blockIdx.y * BM;
    const int n0 = blockIdx.x * BN;
    const int tid = threadIdx.x;
    const int tn = tid % (BN / TN);
    const int tm = tid / (BN / TN);

    float acc[TM][TN];
#pragma unroll
    for (int i = 0; i < TM; i++)
#pragma unroll
        for (int j = 0; j < TN; j++) acc[i][j] = 0.0f;

    for (int k0 = 0; k0 < Kdim; k0 += BK) {
        // load A tile: BK*BM/4 float4 slots
#pragma unroll
        for (int i = tid; i < BK * BM / 4; i += 256) {
            int kk = i / (BM / 4);
            int mv = i % (BM / 4);
            *reinterpret_cast<float4*>(&As[kk][mv * 4]) =
                *reinterpret_cast<const float4*>(&A[(size_t)(k0 + kk) * lda + m0 + mv * 4]);
        }
#pragma unroll
        for (int i = tid; i < BK * BN / 4; i += 256) {
            int kk = i / (BN / 4);
            int nv = i % (BN / 4);
            *reinterpret_cast<float4*>(&Bs[kk][nv * 4]) =
                *reinterpret_cast<const float4*>(&B[(size_t)(k0 + kk) * ldb + n0 + nv * 4]);
        }
        __syncthreads();
#pragma unroll
        for (int kk = 0; kk < BK; kk++) {
            float a[TM], b[TN];
#pragma unroll
            for (int i = 0; i < TM; i++) a[i] = As[kk][tm * TM + i];
#pragma unroll
            for (int j = 0; j < TN; j++) b[j] = Bs[kk][tn * TN + j];
#pragma unroll
            for (int i = 0; i < TM; i++)
#pragma unroll
                for (int j = 0; j < TN; j++)
                    acc[i][j] = fmaf(a[i], b[j], acc[i][j]);
        }
        __syncthreads();
    }
#pragma unroll
    for (int i = 0; i < TM; i++) {
#pragma unroll
        for (int j = 0; j < TN; j += 4) {
            float4 v = make_float4(acc[i][j], acc[i][j + 1], acc[i][j + 2], acc[i][j + 3]);
            *reinterpret_cast<float4*>(&Cm[(size_t)(m0 + tm * TM + i) * ldc + n0 + tn * TN + j]) = v;
        }
    }
}

// ---------------------------------------------------------------------------
// GEMM NN: Out[m,n] (+)= sum_k A[m*lda + k] * B[k*ldb + n]
// Optional split-K via blockIdx.z + atomicAdd accumulation.
// BM=BN=64, BK=16, 256 threads, 4x4 microtile.
// ---------------------------------------------------------------------------
template<int BM, int BN, int BK, int TM, int TN, bool ATOMIC>
__global__ void __launch_bounds__(256, 4) gemm_nn_kernel(
    const float* __restrict__ A, int lda,
    const float* __restrict__ B, int ldb,
    float* __restrict__ Cm, int ldc,
    int Kdim, int kChunk)
{
    __shared__ float As[BK][BM + 1];
    __shared__ float Bs[BK][BN];
    const int m0 = blockIdx.y * BM;
    const int n0 = blockIdx.x * BN;
    const int kBegin = blockIdx.z * kChunk;
    const int kEnd = min(Kdim, kBegin + kChunk);
    const int tid = threadIdx.x;
    const int tn = tid % (BN / TN);
    const int tm = tid / (BN / TN);

    float acc[TM][TN];
#pragma unroll
    for (int i = 0; i < TM; i++)
#pragma unroll
        for (int j = 0; j < TN; j++) acc[i][j] = 0.0f;

    for (int k0 = kBegin; k0 < kEnd; k0 += BK) {
        // A[m,k] -> As[k][m] (transposed store, +1 pad kills conflicts)
#pragma unroll
        for (int i = tid; i < BK * BM; i += 256) {
            int kk = i % BK;
            int mm = i / BK;
            As[kk][mm] = A[(size_t)(m0 + mm) * lda + k0 + kk];
        }
#pragma unroll
        for (int i = tid; i < BK * BN / 4; i += 256) {
            int kk = i / (BN / 4);
            int nv = i % (BN / 4);
            *reinterpret_cast<float4*>(&Bs[kk][nv * 4]) =
                *reinterpret_cast<const float4*>(&B[(size_t)(k0 + kk) * ldb + n0 + nv * 4]);
        }
        __syncthreads();
#pragma unroll
        for (int kk = 0; kk < BK; kk++) {
            float a[TM], b[TN];
#pragma unroll
            for (int i = 0; i < TM; i++) a[i] = As[kk][tm * TM + i];
#pragma unroll
            for (int j = 0; j < TN; j++) b[j] = Bs[kk][tn * TN + j];
#pragma unroll
            for (int i = 0; i < TM; i++)
#pragma unroll
                for (int j = 0; j < TN; j++)
                    acc[i][j] = fmaf(a[i], b[j], acc[i][j]);
        }
        __syncthreads();
    }
#pragma unroll
    for (int i = 0; i < TM; i++)
#pragma unroll
        for (int j = 0; j < TN; j++) {
            float* p = &Cm[(size_t)(m0 + tm * TM + i) * ldc + n0 + tn * TN + j];
            if (ATOMIC) atomicAdd(p, acc[i][j]);
            else        *p = acc[i][j];
        }
}

// ---------------------------------------------------------------------------
// Row-wise softmax with logit scaling: row <- softmax(row * scale)
// One block per row; NE = cols / NT elements per thread, kept in registers.
// ---------------------------------------------------------------------------
__device__ __forceinline__ float warpMax(float v) {
#pragma unroll
    for (int o = 16; o > 0; o >>= 1) v = fmaxf(v, __shfl_xor_sync(0xffffffffu, v, o));
    return v;
}
__device__ __forceinline__ float warpSum(float v) {
#pragma unroll
    for (int o = 16; o > 0; o >>= 1) v += __shfl_xor_sync(0xffffffffu, v, o);
    return v;
}

template<int NT, int NE>
__global__ void __launch_bounds__(NT) softmax_row_kernel(float* __restrict__ data, int cols, float scale)
{
    float* row = data + (size_t)blockIdx.x * cols;
    __shared__ float sred[32];
    const int tid = threadIdx.x;
    const int lane = tid & 31;
    const int wid = tid >> 5;
    constexpr int NW = NT / 32;

    float v[NE];
    float m = -1e30f;
#pragma unroll
    for (int e = 0; e < NE; e++) {
        v[e] = row[tid + e * NT] * scale;
        m = fmaxf(m, v[e]);
    }
    m = warpMax(m);
    if (lane == 0) sred[wid] = m;
    __syncthreads();
    if (wid == 0) {
        float t = (lane < NW) ? sred[lane] : -1e30f;
        t = warpMax(t);
        if (lane == 0) sred[0] = t;
    }
    __syncthreads();
    m = sred[0];
    __syncthreads();

    float s = 0.0f;
#pragma unroll
    for (int e = 0; e < NE; e++) {
        v[e] = __expf(v[e] - m);
        s += v[e];
    }
    s = warpSum(s);
    if (lane == 0) sred[wid] = s;
    __syncthreads();
    if (wid == 0) {
        float t = (lane < NW) ? sred[lane] : 0.0f;
        t = warpSum(t);
        if (lane == 0) sred[0] = t;
    }
    __syncthreads();
    float inv = 1.0f / sred[0];
#pragma unroll
    for (int e = 0; e < NE; e++)
        row[tid + e * NT] = v[e] * inv;
}

__global__ void zero_kernel(float* __restrict__ p, int n)
{
    int i = blockIdx.x * blockDim.x + threadIdx.x;
    if (i < n) p[i] = 0.0f;
}

// ---------------------------------------------------------------------------
// Launch
// ---------------------------------------------------------------------------
extern "C" void kernel_launch(void* const* d_in, const int* in_sizes, int n_in,
                              void* d_out, int out_size)
{
    (void)in_sizes; (void)n_in; (void)out_size;
    const float* query = (const float*)d_in[0]; // (C, HW)
    const float* key   = (const float*)d_in[1]; // (C, S)
    const float* value = (const float*)d_in[2]; // (C, S)
    const float* Wq    = (const float*)d_in[3]; // (C, C) [o][c]
    const float* Wk    = (const float*)d_in[4];
    const float* Wv    = (const float*)d_in[5];
    float* out = (float*)d_out;                 // (C, HW)

    float *WqT, *WkT, *Q, *Kt, *T, *M;
    cudaGetSymbolAddress((void**)&WqT, g_WqT);
    cudaGetSymbolAddress((void**)&WkT, g_WkT);
    cudaGetSymbolAddress((void**)&Q,   g_Q);
    cudaGetSymbolAddress((void**)&Kt,  g_Kt);
    cudaGetSymbolAddress((void**)&T,   g_T);
    cudaGetSymbolAddress((void**)&M,   g_M);

    // 1) Transpose weights for coalesced TN GEMM loads
    transpose256_kernel<<<dim3(8, 8), dim3(32, 8)>>>(Wq, WqT);
    transpose256_kernel<<<dim3(8, 8), dim3(32, 8)>>>(Wk, WkT);

    // 2) q logits: Q[o,hw] = sum_c WqT[c,o] * query[c,hw]   (M=256, N=4096, K=256)
    gemm_tn_kernel<128, 128, 8, 8, 8>
        <<<dim3(HW_ / 128, C_ / 128), 256>>>(WqT, C_, query, HW_, Q, HW_, C_);

    // 3) q softmax over hw (rows of 4096)
    softmax_row_kernel<256, 16><<<C_, 256>>>(Q, HW_, INV_TEMP);

    // 4) k logits transposed: Kt[j,o] = sum_c key[c,S0+j] * WkT[c,o]  (M=20480, N=256, K=256)
    gemm_tn_kernel<128, 128, 8, 8, 8>
        <<<dim3(C_ / 128, SA_ / 128), 256>>>(key + S0_, S_, WkT, C_, Kt, C_, C_);

    // 5) k softmax over channels (rows of 256)
    softmax_row_kernel<256, 1><<<SA_, 256>>>(Kt, C_, INV_TEMP);

    // 6) T[a,c'] = sum_j value[a,S0+j] * Kt[j,c']  (M=256, N=256, K=20480, split-K=10)
    zero_kernel<<<(C_ * C_ + 255) / 256, 256>>>(T, C_ * C_);
    gemm_nn_kernel<64, 64, 16, 4, 4, true>
        <<<dim3(C_ / 64, C_ / 64, 10), 256>>>(value + S0_, S_, Kt, C_, T, C_, SA_, SA_ / 10);

    // 7) M = Wv @ T  (256x256x256)
    gemm_nn_kernel<64, 64, 16, 4, 4, false>
        <<<dim3(C_ / 64, C_ / 64, 1), 256>>>(Wv, C_, T, C_, M, C_, C_, C_);

    // 8) out = M @ Qs  (M=256, N=4096, K=256)
    gemm_nn_kernel<64, 64, 16, 4, 4, false>
        <<<dim3(HW_ / 64, C_ / 64, 1), 256>>>(M, C_, Q, HW_, out, HW_, C_, C_);
}

// round 3
// speedup vs baseline: 2.2473x; 2.2473x over previous
#include <cuda_runtime.h>
#include <cuda_bf16.h>
#include <cstdint>

// ---------------------------------------------------------------------------
// Problem constants (B=1)
// ---------------------------------------------------------------------------
static constexpr int C_   = 256;
static constexpr int HW_  = 4096;     // 64*64
static constexpr int S_   = 32768;    // 8*64*64
static constexpr int SA_  = 20480;    // 5*64*64 active (last 5 frames)
static constexpr int S0_  = S_ - SA_; // 12288
static constexpr float INV_TEMP = 10.0f;

// ---------------------------------------------------------------------------
// Device scratch
// ---------------------------------------------------------------------------
__device__ __align__(16) __nv_bfloat16 g_keyT_hi[SA_ * C_];   // [j][c]
__device__ __align__(16) __nv_bfloat16 g_keyT_lo[SA_ * C_];
__device__ __align__(16) __nv_bfloat16 g_val_hi [C_ * SA_];   // [a][j]
__device__ __align__(16) __nv_bfloat16 g_val_lo [C_ * SA_];
__device__ __align__(16) __nv_bfloat16 g_KsT_hi [C_ * SA_];   // [o][j] (k-softmaxed, transposed)
__device__ __align__(16) __nv_bfloat16 g_KsT_lo [C_ * SA_];
__device__ __align__(16) __nv_bfloat16 g_qT_hi  [HW_ * C_];   // [hw][c]
__device__ __align__(16) __nv_bfloat16 g_qT_lo  [HW_ * C_];
__device__ __align__(16) __nv_bfloat16 g_QsT_hi [HW_ * C_];   // [hw][o]
__device__ __align__(16) __nv_bfloat16 g_QsT_lo [HW_ * C_];
__device__ __align__(16) __nv_bfloat16 g_Wq_hi[C_ * C_], g_Wq_lo[C_ * C_];
__device__ __align__(16) __nv_bfloat16 g_Wk_hi[C_ * C_], g_Wk_lo[C_ * C_];
__device__ __align__(16) __nv_bfloat16 g_Wv_hi[C_ * C_], g_Wv_lo[C_ * C_];
__device__ __align__(16) __nv_bfloat16 g_T2T_hi[C_ * C_], g_T2T_lo[C_ * C_];
__device__ __align__(16) __nv_bfloat16 g_G_hi [C_ * C_], g_G_lo [C_ * C_];
__device__ __align__(16) float g_Klog[SA_ * C_];   // k logits [j][o]
__device__ __align__(16) float g_Qlog[C_ * HW_];   // q logits -> softmaxed in place
__device__ __align__(16) float g_T2  [C_ * C_];    // split-K accumulator [a][o]
__device__ __align__(16) float g_G   [C_ * C_];    // G[c][o]

// ---------------------------------------------------------------------------
// PTX helpers (compute_100-safe: cp.async / ldmatrix / mma.sync only)
// ---------------------------------------------------------------------------
__device__ __forceinline__ uint32_t smem_u32(const void* p) {
    uint32_t a;
    asm("{ .reg .u64 t; cvta.to.shared.u64 t, %1; cvt.u32.u64 %0, t; }" : "=r"(a) : "l"(p));
    return a;
}
__device__ __forceinline__ void cp16(uint32_t dst, const void* src) {
    asm volatile("cp.async.cg.shared.global [%0], [%1], 16;" :: "r"(dst), "l"(src));
}
__device__ __forceinline__ void cp_commit() {
    asm volatile("cp.async.commit_group;" ::: "memory");
}
__device__ __forceinline__ void ldm_x4(uint32_t* r, uint32_t addr) {
    asm volatile("ldmatrix.sync.aligned.m8n8.x4.shared.b16 {%0,%1,%2,%3}, [%4];"
                 : "=r"(r[0]), "=r"(r[1]), "=r"(r[2]), "=r"(r[3]) : "r"(addr));
}
__device__ __forceinline__ void mma16816(float* c, const uint32_t* a, const uint32_t* b) {
    asm volatile(
        "mma.sync.aligned.m16n8k16.row.col.f32.bf16.bf16.f32 "
        "{%0,%1,%2,%3}, {%4,%5,%6,%7}, {%8,%9}, {%0,%1,%2,%3};"
        : "+f"(c[0]), "+f"(c[1]), "+f"(c[2]), "+f"(c[3])
        : "r"(a[0]), "r"(a[1]), "r"(a[2]), "r"(a[3]), "r"(b[0]), "r"(b[1]));
}

// ---------------------------------------------------------------------------
// fp32 -> bf16 hi/lo split conversion (no transpose)
// ---------------------------------------------------------------------------
__global__ void conv_hilo_kernel(const float* __restrict__ src, int srcLd,
                                 __nv_bfloat16* __restrict__ hi,
                                 __nv_bfloat16* __restrict__ lo,
                                 int dstLd, int rows, int cols)
{
    int colq = cols >> 2;
    int total = rows * colq;
    for (int idx = blockIdx.x * blockDim.x + threadIdx.x; idx < total;
         idx += gridDim.x * blockDim.x) {
        int r = idx / colq;
        int c4 = (idx - r * colq) << 2;
        float4 v = *reinterpret_cast<const float4*>(src + (size_t)r * srcLd + c4);
        float vv[4] = {v.x, v.y, v.z, v.w};
        __nv_bfloat16 h[4], l[4];
#pragma unroll
        for (int i = 0; i < 4; i++) {
            h[i] = __float2bfloat16(vv[i]);
            l[i] = __float2bfloat16(vv[i] - __bfloat162float(h[i]));
        }
        uint32_t ph  = (uint32_t)__bfloat16_as_ushort(h[0]) | ((uint32_t)__bfloat16_as_ushort(h[1]) << 16);
        uint32_t ph2 = (uint32_t)__bfloat16_as_ushort(h[2]) | ((uint32_t)__bfloat16_as_ushort(h[3]) << 16);
        uint32_t pl  = (uint32_t)__bfloat16_as_ushort(l[0]) | ((uint32_t)__bfloat16_as_ushort(l[1]) << 16);
        uint32_t pl2 = (uint32_t)__bfloat16_as_ushort(l[2]) | ((uint32_t)__bfloat16_as_ushort(l[3]) << 16);
        *reinterpret_cast<uint2*>(hi + (size_t)r * dstLd + c4) = make_uint2(ph, ph2);
        *reinterpret_cast<uint2*>(lo + (size_t)r * dstLd + c4) = make_uint2(pl, pl2);
    }
}

// ---------------------------------------------------------------------------
// fp32 [R][C] -> bf16 hi/lo [C][R] (transpose + split)
// grid = (C/32, R/32), block = (32, 8)
// ---------------------------------------------------------------------------
__global__ void convT_kernel(const float* __restrict__ src, int srcLd,
                             __nv_bfloat16* __restrict__ hi,
                             __nv_bfloat16* __restrict__ lo, int dstLd)
{
    __shared__ float t[32][33];
    int c0 = blockIdx.x * 32, r0 = blockIdx.y * 32;
    int tx = threadIdx.x, ty = threadIdx.y;
#pragma unroll
    for (int i = 0; i < 32; i += 8)
        t[ty + i][tx] = src[(size_t)(r0 + ty + i) * srcLd + c0 + tx];
    __syncthreads();
#pragma unroll
    for (int i = 0; i < 32; i += 8) {
        float v = t[tx][ty + i];
        __nv_bfloat16 h = __float2bfloat16(v);
        __nv_bfloat16 l = __float2bfloat16(v - __bfloat162float(h));
        size_t o = (size_t)(c0 + ty + i) * dstLd + r0 + tx;
        hi[o] = h;
        lo[o] = l;
    }
}

// ---------------------------------------------------------------------------
// Tensor-core GEMM via mma.sync (bf16x3 split):
//   D[m0..m0+127, n0..n0+255 over grid.x] (+)= sum_k A[m,k]*B[n,k]
// A,B K-major bf16 (hi+lo). BM=BN=128, BK=32, 256 threads, double-buffered
// cp.async, ldmatrix operand loads, SMEM rows padded to 80B (conflict-free).
// EPI: 0 = fp32 store, 2 = fp32 atomicAdd (split-K).
// ---------------------------------------------------------------------------
static constexpr int ARR_BYTES   = 128 * 80;       // one operand tile
static constexpr int STAGE_BYTES = 4 * ARR_BYTES;  // Ah, Al, Bh, Bl
static constexpr int GEMM_SMEM   = 2 * STAGE_BYTES; // 81920

__device__ __forceinline__ void load_stage(uint32_t sb, int stage,
    const __nv_bfloat16* __restrict__ Ah, const __nv_bfloat16* __restrict__ Al,
    int aLd, int m0,
    const __nv_bfloat16* __restrict__ Bh, const __nv_bfloat16* __restrict__ Bl,
    int bLd, int n0, int kOff, int tid)
{
    uint32_t base = sb + stage * STAGE_BYTES;
#pragma unroll
    for (int i = 0; i < 8; i++) {
        int idx = tid + i * 256;
        int arr = idx >> 9;
        int rem = idx & 511;
        int row = rem >> 2;
        int ch  = rem & 3;
        const __nv_bfloat16* g;
        int ld, rb;
        if (arr == 0)      { g = Ah; ld = aLd; rb = m0; }
        else if (arr == 1) { g = Al; ld = aLd; rb = m0; }
        else if (arr == 2) { g = Bh; ld = bLd; rb = n0; }
        else               { g = Bl; ld = bLd; rb = n0; }
        uint32_t dst = base + arr * ARR_BYTES + row * 80 + ch * 16;
        cp16(dst, g + (size_t)(rb + row) * ld + kOff + ch * 8);
    }
}

template<int EPI>
__global__ void __launch_bounds__(256, 1) gemm_mma_kernel(
    const __nv_bfloat16* __restrict__ Ah, const __nv_bfloat16* __restrict__ Al, int aLd,
    const __nv_bfloat16* __restrict__ Bh, const __nv_bfloat16* __restrict__ Bl, int bLd,
    float* __restrict__ out, int outLd, int kPerCta)
{
    extern __shared__ char smem[];
    uint32_t sb = smem_u32(smem);
    const int tid  = threadIdx.x;
    const int wid  = tid >> 5;
    const int lane = tid & 31;
    const int m0 = blockIdx.y * 128;
    const int n0 = blockIdx.x * 128;
    const int kStart = blockIdx.z * kPerCta;
    const int nChunks = kPerCta >> 5;

    const int wm = wid >> 2;        // 0..1
    const int wn = wid & 3;         // 0..3
    const int mBase = wm * 64;
    const int nBase = wn * 32;
    const int g = lane >> 2;
    const int t = lane & 3;
    const int mat = lane >> 3;
    const int r   = lane & 7;

    // ldmatrix lane-address bases (within a stage)
    // A matrices order: (r0-7,k0-7),(r8-15,k0-7),(r0-7,k8-15),(r8-15,k8-15)
    const uint32_t aOff = (uint32_t)(mBase + (mat & 1) * 8 + r) * 80 + (mat >> 1) * 16;
    // B matrices order (per p): (n0-7,k0-7),(n0-7,k8-15),(n8-15,k0-7),(n8-15,k8-15)
    const uint32_t bOff = 2 * ARR_BYTES + (uint32_t)(nBase + (mat >> 1) * 8 + r) * 80 + (mat & 1) * 16;

    float acc[4][4][4];
#pragma unroll
    for (int i = 0; i < 4; i++)
#pragma unroll
        for (int j = 0; j < 4; j++)
#pragma unroll
            for (int e = 0; e < 4; e++) acc[i][j][e] = 0.0f;

    load_stage(sb, 0, Ah, Al, aLd, m0, Bh, Bl, bLd, n0, kStart, tid);
    cp_commit();

    for (int ch = 0; ch < nChunks; ch++) {
        if (ch + 1 < nChunks) {
            load_stage(sb, (ch + 1) & 1, Ah, Al, aLd, m0, Bh, Bl, bLd, n0,
                       kStart + (ch + 1) * 32, tid);
            cp_commit();
            asm volatile("cp.async.wait_group 1;" ::: "memory");
        } else {
            asm volatile("cp.async.wait_group 0;" ::: "memory");
        }
        __syncthreads();

        const uint32_t stageBase = sb + (ch & 1) * STAGE_BYTES;
#pragma unroll
        for (int kk = 0; kk < 2; kk++) {
            const uint32_t colOff = kk * 32;
            uint32_t bh[8], bl[8], ah[4][4], al[4][4];
#pragma unroll
            for (int p = 0; p < 2; p++) {
                ldm_x4(&bh[p * 4], stageBase + bOff + p * 1280 + colOff);
                ldm_x4(&bl[p * 4], stageBase + ARR_BYTES + bOff + p * 1280 + colOff);
            }
#pragma unroll
            for (int mt = 0; mt < 4; mt++) {
                ldm_x4(ah[mt], stageBase + aOff + mt * 1280 + colOff);
                ldm_x4(al[mt], stageBase + ARR_BYTES + aOff + mt * 1280 + colOff);
            }
#pragma unroll
            for (int mt = 0; mt < 4; mt++) {
#pragma unroll
                for (int nt = 0; nt < 4; nt++) {
                    const uint32_t* bhp = &bh[(nt >> 1) * 4 + (nt & 1) * 2];
                    const uint32_t* blp = &bl[(nt >> 1) * 4 + (nt & 1) * 2];
                    mma16816(acc[mt][nt], ah[mt], bhp);
                    mma16816(acc[mt][nt], ah[mt], blp);
                    mma16816(acc[mt][nt], al[mt], bhp);
                }
            }
        }
        __syncthreads();
    }

    // Epilogue
#pragma unroll
    for (int mt = 0; mt < 4; mt++) {
#pragma unroll
        for (int nt = 0; nt < 4; nt++) {
            int row = m0 + mBase + mt * 16 + g;
            int col = n0 + nBase + nt * 8 + 2 * t;
            float* p0 = out + (size_t)row * outLd + col;
            float* p1 = out + (size_t)(row + 8) * outLd + col;
            if (EPI == 0) {
                *reinterpret_cast<float2*>(p0) = make_float2(acc[mt][nt][0], acc[mt][nt][1]);
                *reinterpret_cast<float2*>(p1) = make_float2(acc[mt][nt][2], acc[mt][nt][3]);
            } else {
                atomicAdd(p0,     acc[mt][nt][0]);
                atomicAdd(p0 + 1, acc[mt][nt][1]);
                atomicAdd(p1,     acc[mt][nt][2]);
                atomicAdd(p1 + 1, acc[mt][nt][3]);
            }
        }
    }
}

// ---------------------------------------------------------------------------
// k-softmax (over 256 channels) + transpose + bf16 hi/lo split:
//   Klog [j][o] (SA x 256) -> KsT_hi/lo [o][j] (256 x SA)
// One block per 32 j-rows. smem pad 261 -> conflict-free transposed reads.
// ---------------------------------------------------------------------------
__global__ void __launch_bounds__(256) ksoftmaxT_kernel(
    const float* __restrict__ Klog,
    __nv_bfloat16* __restrict__ KsT_hi, __nv_bfloat16* __restrict__ KsT_lo)
{
    __shared__ float s[32][261];
    const int tid = threadIdx.x;
    const int j0 = blockIdx.x * 32;

    // load 32x256 tile (coalesced)
#pragma unroll
    for (int i = 0; i < 32; i++)
        s[i][tid] = Klog[(size_t)(j0 + i) * C_ + tid];
    __syncthreads();

    // each warp: 4 rows sequentially; 32 lanes x 8 cols each
    const int wid = tid >> 5, lane = tid & 31;
#pragma unroll
    for (int rr = 0; rr < 4; rr++) {
        int row = wid * 4 + rr;
        float v[8], m = -1e30f;
#pragma unroll
        for (int e = 0; e < 8; e++) {
            v[e] = s[row][lane + e * 32] * INV_TEMP;
            m = fmaxf(m, v[e]);
        }
#pragma unroll
        for (int o = 16; o > 0; o >>= 1) m = fmaxf(m, __shfl_xor_sync(0xffffffffu, m, o));
        float sum = 0.0f;
#pragma unroll
        for (int e = 0; e < 8; e++) {
            v[e] = __expf(v[e] - m);
            sum += v[e];
        }
#pragma unroll
        for (int o = 16; o > 0; o >>= 1) sum += __shfl_xor_sync(0xffffffffu, sum, o);
        float inv = 1.0f / sum;
#pragma unroll
        for (int e = 0; e < 8; e++)
            s[row][lane + e * 32] = v[e] * inv;
    }
    __syncthreads();

    // transposed writeout: 32 consecutive threads write 32 contiguous j for one o
    for (int i = tid; i < 32 * 256; i += 256) {
        int o = i >> 5, jj = i & 31;
        float v = s[jj][o];
        __nv_bfloat16 h = __float2bfloat16(v);
        __nv_bfloat16 l = __float2bfloat16(v - __bfloat162float(h));
        size_t dst = (size_t)o * SA_ + j0 + jj;
        KsT_hi[dst] = h;
        KsT_lo[dst] = l;
    }
}

// ---------------------------------------------------------------------------
// q softmax (rows of 4096)
// ---------------------------------------------------------------------------
template<int NT, int NE>
__global__ void __launch_bounds__(NT) softmax_row_kernel(float* __restrict__ data, int cols, float scale)
{
    float* row = data + (size_t)blockIdx.x * cols;
    __shared__ float sred[32];
    const int tid = threadIdx.x;
    const int lane = tid & 31;
    const int wid = tid >> 5;
    constexpr int NW = NT / 32;

    float v[NE];
    float m = -1e30f;
#pragma unroll
    for (int e = 0; e < NE; e++) {
        v[e] = row[tid + e * NT] * scale;
        m = fmaxf(m, v[e]);
    }
#pragma unroll
    for (int o = 16; o > 0; o >>= 1) m = fmaxf(m, __shfl_xor_sync(0xffffffffu, m, o));
    if (lane == 0) sred[wid] = m;
    __syncthreads();
    if (wid == 0) {
        float tv = (lane < NW) ? sred[lane] : -1e30f;
#pragma unroll
        for (int o = 16; o > 0; o >>= 1) tv = fmaxf(tv, __shfl_xor_sync(0xffffffffu, tv, o));
        if (lane == 0) sred[0] = tv;
    }
    __syncthreads();
    m = sred[0];
    __syncthreads();

    float sum = 0.0f;
#pragma unroll
    for (int e = 0; e < NE; e++) {
        v[e] = __expf(v[e] - m);
        sum += v[e];
    }
#pragma unroll
    for (int o = 16; o > 0; o >>= 1) sum += __shfl_xor_sync(0xffffffffu, sum, o);
    if (lane == 0) sred[wid] = sum;
    __syncthreads();
    if (wid == 0) {
        float tv = (lane < NW) ? sred[lane] : 0.0f;
#pragma unroll
        for (int o = 16; o > 0; o >>= 1) tv += __shfl_xor_sync(0xffffffffu, tv, o);
        if (lane == 0) sred[0] = tv;
    }
    __syncthreads();
    float inv = 1.0f / sred[0];
#pragma unroll
    for (int e = 0; e < NE; e++)
        row[tid + e * NT] = v[e] * inv;
}

__global__ void zero_kernel(float* __restrict__ p, int n)
{
    int i = blockIdx.x * blockDim.x + threadIdx.x;
    if (i < n) p[i] = 0.0f;
}

// ---------------------------------------------------------------------------
// Launch
// ---------------------------------------------------------------------------
extern "C" void kernel_launch(void* const* d_in, const int* in_sizes, int n_in,
                              void* d_out, int out_size)
{
    (void)in_sizes; (void)n_in; (void)out_size;
    const float* query = (const float*)d_in[0]; // (C, HW)
    const float* key   = (const float*)d_in[1]; // (C, S)
    const float* value = (const float*)d_in[2]; // (C, S)
    const float* Wq    = (const float*)d_in[3]; // (C, C)
    const float* Wk    = (const float*)d_in[4];
    const float* Wv    = (const float*)d_in[5];
    float* out = (float*)d_out;                 // (C, HW)

    cudaFuncSetAttribute(gemm_mma_kernel<0>, cudaFuncAttributeMaxDynamicSharedMemorySize, GEMM_SMEM);
    cudaFuncSetAttribute(gemm_mma_kernel<2>, cudaFuncAttributeMaxDynamicSharedMemorySize, GEMM_SMEM);

    __nv_bfloat16 *keyT_hi, *keyT_lo, *val_hi, *val_lo, *KsT_hi, *KsT_lo;
    __nv_bfloat16 *qT_hi, *qT_lo, *QsT_hi, *QsT_lo;
    __nv_bfloat16 *Wq_hi, *Wq_lo, *Wk_hi, *Wk_lo, *Wv_hi, *Wv_lo;
    __nv_bfloat16 *T2T_hi, *T2T_lo, *G_hi, *G_lo;
    float *Klog, *Qlog, *T2, *G;
    cudaGetSymbolAddress((void**)&keyT_hi, g_keyT_hi);
    cudaGetSymbolAddress((void**)&keyT_lo, g_keyT_lo);
    cudaGetSymbolAddress((void**)&val_hi,  g_val_hi);
    cudaGetSymbolAddress((void**)&val_lo,  g_val_lo);
    cudaGetSymbolAddress((void**)&KsT_hi,  g_KsT_hi);
    cudaGetSymbolAddress((void**)&KsT_lo,  g_KsT_lo);
    cudaGetSymbolAddress((void**)&qT_hi,   g_qT_hi);
    cudaGetSymbolAddress((void**)&qT_lo,   g_qT_lo);
    cudaGetSymbolAddress((void**)&QsT_hi,  g_QsT_hi);
    cudaGetSymbolAddress((void**)&QsT_lo,  g_QsT_lo);
    cudaGetSymbolAddress((void**)&Wq_hi,   g_Wq_hi);
    cudaGetSymbolAddress((void**)&Wq_lo,   g_Wq_lo);
    cudaGetSymbolAddress((void**)&Wk_hi,   g_Wk_hi);
    cudaGetSymbolAddress((void**)&Wk_lo,   g_Wk_lo);
    cudaGetSymbolAddress((void**)&Wv_hi,   g_Wv_hi);
    cudaGetSymbolAddress((void**)&Wv_lo,   g_Wv_lo);
    cudaGetSymbolAddress((void**)&T2T_hi,  g_T2T_hi);
    cudaGetSymbolAddress((void**)&T2T_lo,  g_T2T_lo);
    cudaGetSymbolAddress((void**)&G_hi,    g_G_hi);
    cudaGetSymbolAddress((void**)&G_lo,    g_G_lo);
    cudaGetSymbolAddress((void**)&Klog,    g_Klog);
    cudaGetSymbolAddress((void**)&Qlog,    g_Qlog);
    cudaGetSymbolAddress((void**)&T2,      g_T2);
    cudaGetSymbolAddress((void**)&G,       g_G);

    // ---- conversions ----
    conv_hilo_kernel<<<64, 256>>>(Wq, C_, Wq_hi, Wq_lo, C_, C_, C_);
    conv_hilo_kernel<<<64, 256>>>(Wk, C_, Wk_hi, Wk_lo, C_, C_, C_);
    conv_hilo_kernel<<<64, 256>>>(Wv, C_, Wv_hi, Wv_lo, C_, C_, C_);
    convT_kernel<<<dim3(SA_ / 32, C_ / 32), dim3(32, 8)>>>(key + S0_, S_, keyT_hi, keyT_lo, C_);
    conv_hilo_kernel<<<2048, 256>>>(value + S0_, S_, val_hi, val_lo, SA_, C_, SA_);
    convT_kernel<<<dim3(HW_ / 32, C_ / 32), dim3(32, 8)>>>(query, HW_, qT_hi, qT_lo, C_);

    // ---- GEMM1: Klog[j][o] = keyT[j][:] . Wk[o][:]   (M=SA, N=256, K=256) ----
    gemm_mma_kernel<0><<<dim3(C_ / 128, SA_ / 128, 1), 256, GEMM_SMEM>>>(
        keyT_hi, keyT_lo, C_, Wk_hi, Wk_lo, C_, Klog, C_, C_);

    // ---- k softmax over channels + transpose -> KsT [o][j] bf16 hi/lo ----
    ksoftmaxT_kernel<<<SA_ / 32, 256>>>(Klog, KsT_hi, KsT_lo);

    // ---- GEMM2: Qlog[o][hw] = Wq[o][:] . qT[hw][:]   (M=256, N=HW, K=256) ----
    gemm_mma_kernel<0><<<dim3(HW_ / 128, C_ / 128, 1), 256, GEMM_SMEM>>>(
        Wq_hi, Wq_lo, C_, qT_hi, qT_lo, C_, Qlog, HW_, C_);

    // ---- q softmax over hw, then transpose/split -> QsT [hw][o] ----
    softmax_row_kernel<256, 16><<<C_, 256>>>(Qlog, HW_, INV_TEMP);
    convT_kernel<<<dim3(HW_ / 32, C_ / 32), dim3(32, 8)>>>(Qlog, HW_, QsT_hi, QsT_lo, C_);

    // ---- GEMM3: T2[a][o] = sum_j val[a][j]*Ks[j][o]  split-K 32, atomic ----
    zero_kernel<<<(C_ * C_ + 255) / 256, 256>>>(T2, C_ * C_);
    gemm_mma_kernel<2><<<dim3(C_ / 128, C_ / 128, 32), 256, GEMM_SMEM>>>(
        val_hi, val_lo, SA_, KsT_hi, KsT_lo, SA_, T2, C_, SA_ / 32);

    // T2 -> T2T [o][a] bf16 hi/lo
    convT_kernel<<<dim3(C_ / 32, C_ / 32), dim3(32, 8)>>>(T2, C_, T2T_hi, T2T_lo, C_);

    // ---- GEMM4: G[c][o] = sum_a Wv[c][a]*T2T[o][a]   (256^3) ----
    gemm_mma_kernel<0><<<dim3(C_ / 128, C_ / 128, 1), 256, GEMM_SMEM>>>(
        Wv_hi, Wv_lo, C_, T2T_hi, T2T_lo, C_, G, C_, C_);

    conv_hilo_kernel<<<64, 256>>>(G, C_, G_hi, G_lo, C_, C_, C_);

    // ---- GEMM5: out[c][hw] = sum_o G[c][o]*Qs[o][hw] (M=256, N=HW, K=256) ----
    gemm_mma_kernel<0><<<dim3(HW_ / 128, C_ / 128, 1), 256, GEMM_SMEM>>>(
        G_hi, G_lo, C_, QsT_hi, QsT_lo, C_, out, HW_, C_);
}